// round 1
// baseline (speedup 1.0000x reference)
#include <cuda_runtime.h>
#include <math.h>

#define D 1024
#define B 16
#define L 2048
#define N (B*L)              // 32768 tokens
#define NC 16                // scan chunks
#define CL (L/NC)            // 128

static const size_t ND = (size_t)N * D;

// ---------------- scratch (static __device__, no allocations) ----------------
__device__ float g_h[(size_t)N*D];        // rmsnorm1 output / rmsnorm2 output (reused)
__device__ float g_gate[(size_t)N*D];
__device__ float g_hs[(size_t)N*D];
__device__ float g_r[(size_t)N*D];        // sigmoid(r), then overwritten with a
__device__ float g_i[(size_t)N*D];        // sigmoid(i), then overwritten with s
__device__ float g_hs2[(size_t)N*D];
__device__ float g_g2[(size_t)N*3*D];
__device__ float g_f2[(size_t)N*3*D];     // holds f2*g2 after MUL epilogue
__device__ float g_Agg[B*NC*D];
__device__ float g_Sgg[B*NC*D];
__device__ float g_Cin[B*NC*D];

// ---------------- rmsnorm: one block per row, 256 threads ----------------
__global__ void __launch_bounds__(256) rmsnorm_kernel(const float* __restrict__ x,
                                                      const float* __restrict__ w,
                                                      float* __restrict__ y) {
    int row = blockIdx.x;
    int t = threadIdx.x;
    const float4* xr = (const float4*)(x + (size_t)row * D);
    float4 xv = xr[t];                         // D/4 = 256 float4 per row
    float ss = xv.x*xv.x + xv.y*xv.y + xv.z*xv.z + xv.w*xv.w;
    #pragma unroll
    for (int o = 16; o > 0; o >>= 1) ss += __shfl_xor_sync(0xffffffffu, ss, o);
    __shared__ float red[8];
    if ((t & 31) == 0) red[t >> 5] = ss;
    __syncthreads();
    if (t < 32) {
        float v = (t < 8) ? red[t] : 0.f;
        #pragma unroll
        for (int o = 4; o > 0; o >>= 1) v += __shfl_xor_sync(0xffffffffu, v, o);
        if (t == 0) red[0] = v;
    }
    __syncthreads();
    float scale = rsqrtf(red[0] * (1.0f / (float)D) + 1e-6f);
    const float4* wr = (const float4*)w;
    float4 wv = wr[t];
    float4 ov;
    ov.x = xv.x * scale * wv.x;
    ov.y = xv.y * scale * wv.y;
    ov.z = xv.z * scale * wv.z;
    ov.w = xv.w * scale * wv.w;
    ((float4*)(y + (size_t)row * D))[t] = ov;
}

// ---------------- GEMM: C[M,O] = A[M,K] * W[O,K]^T + bias, epilogue ----------------
// 128x128 block tile, BK=8, 256 threads, 8x8 per thread.
#define EPI_NONE 0
#define EPI_GELU 1
#define EPI_SIG  2
#define EPI_MUL  3
#define EPI_ADD  4

__device__ __forceinline__ float gelu_exact(float v) {
    return 0.5f * v * (1.0f + erff(v * 0.70710678118654752f));
}
__device__ __forceinline__ float sigmoid_f(float v) {
    return 1.0f / (1.0f + expf(-v));
}

template<int EPI>
__global__ void __launch_bounds__(256) gemm_kernel(
    const float* __restrict__ A, const float* __restrict__ W,
    const float* __restrict__ bias, const float* __restrict__ aux,
    float* __restrict__ C, int M, int O, int K)
{
    __shared__ float As[8][132];
    __shared__ float Bs[8][132];
    const int tid = threadIdx.x;
    const int m0 = blockIdx.y * 128;
    const int n0 = blockIdx.x * 128;
    const int tx = tid & 15;       // 0..15 -> output cols tx*8..
    const int ty = tid >> 4;       // 0..15 -> output rows ty*8..
    const int lr = tid >> 1;       // 0..127 tile row for loads
    const int lk = (tid & 1) * 4;  // 0 or 4

    const float* Ag = A + (size_t)(m0 + lr) * K + lk;
    const float* Wg = W + (size_t)(n0 + lr) * K + lk;

    float acc[8][8];
    #pragma unroll
    for (int i = 0; i < 8; i++)
        #pragma unroll
        for (int j = 0; j < 8; j++) acc[i][j] = 0.f;

    for (int kt = 0; kt < K; kt += 8) {
        float4 av = *(const float4*)(Ag + kt);
        float4 bv = *(const float4*)(Wg + kt);
        As[lk+0][lr] = av.x; As[lk+1][lr] = av.y; As[lk+2][lr] = av.z; As[lk+3][lr] = av.w;
        Bs[lk+0][lr] = bv.x; Bs[lk+1][lr] = bv.y; Bs[lk+2][lr] = bv.z; Bs[lk+3][lr] = bv.w;
        __syncthreads();
        #pragma unroll
        for (int k = 0; k < 8; k++) {
            float4 a0 = *(const float4*)&As[k][ty*8];
            float4 a1 = *(const float4*)&As[k][ty*8+4];
            float4 b0 = *(const float4*)&Bs[k][tx*8];
            float4 b1 = *(const float4*)&Bs[k][tx*8+4];
            float ra[8] = {a0.x,a0.y,a0.z,a0.w,a1.x,a1.y,a1.z,a1.w};
            float rb[8] = {b0.x,b0.y,b0.z,b0.w,b1.x,b1.y,b1.z,b1.w};
            #pragma unroll
            for (int i = 0; i < 8; i++)
                #pragma unroll
                for (int j = 0; j < 8; j++)
                    acc[i][j] = fmaf(ra[i], rb[j], acc[i][j]);
        }
        __syncthreads();
    }

    // epilogue
    float bsv[8];
    #pragma unroll
    for (int j = 0; j < 8; j++) bsv[j] = bias[n0 + tx*8 + j];
    #pragma unroll
    for (int i = 0; i < 8; i++) {
        int m = m0 + ty*8 + i;
        size_t rowoff = (size_t)m * O + n0 + tx*8;
        float out[8];
        #pragma unroll
        for (int j = 0; j < 8; j++) {
            float v = acc[i][j] + bsv[j];
            if (EPI == EPI_GELU) v = gelu_exact(v);
            else if (EPI == EPI_SIG)  v = sigmoid_f(v);
            else if (EPI == EPI_MUL)  v = v * aux[rowoff + j];
            else if (EPI == EPI_ADD)  v = v + aux[rowoff + j];
            out[j] = v;
        }
        *(float4*)(C + rowoff)     = make_float4(out[0],out[1],out[2],out[3]);
        *(float4*)(C + rowoff + 4) = make_float4(out[4],out[5],out[6],out[7]);
    }
}

// ---------------- elementwise: a = exp(-8*softplus(alpha)*r); s = sqrt(1-a^2)*hs*i ----------------
__global__ void __launch_bounds__(256) as_kernel(const float* __restrict__ hs,
                                                 const float* __restrict__ r,
                                                 const float* __restrict__ iv,
                                                 const float* __restrict__ alpha,
                                                 float* __restrict__ a_out,
                                                 float* __restrict__ s_out) {
    int idx = blockIdx.x * 256 + threadIdx.x;
    int d = idx & (D - 1);
    float sp = log1pf(expf(alpha[d]));
    float a = expf(-8.0f * sp * r[idx]);
    float s = sqrtf(fmaxf(1.0f - a * a, 0.0f)) * hs[idx] * iv[idx];
    a_out[idx] = a;
    s_out[idx] = s;
}

// ---------------- scan pass 1: per (b, chunk, d) compute A = prod a, S = local scan end ----------------
__global__ void __launch_bounds__(256) scan1_kernel(const float* __restrict__ a,
                                                    const float* __restrict__ s,
                                                    float* __restrict__ Agg,
                                                    float* __restrict__ Sgg) {
    int g = blockIdx.x * 256 + threadIdx.x;      // B*NC*D threads
    int d = g & (D - 1);
    int chunk = (g >> 10) & (NC - 1);
    int b = g >> 14;
    size_t base = ((size_t)b * L + (size_t)chunk * CL) * D + d;
    float Ap = 1.f, S = 0.f;
    for (int t = 0; t < CL; t++) {
        float at = a[base + (size_t)t * D];
        float st = s[base + (size_t)t * D];
        S = fmaf(at, S, st);
        Ap *= at;
    }
    Agg[g] = Ap;
    Sgg[g] = S;
}

// ---------------- scan pass 2: sequential combine over chunks per channel ----------------
__global__ void __launch_bounds__(256) scan2_kernel(const float* __restrict__ Agg,
                                                    const float* __restrict__ Sgg,
                                                    float* __restrict__ Cin) {
    int g = blockIdx.x * 256 + threadIdx.x;      // B*D threads
    int d = g & (D - 1);
    int b = g >> 10;
    float carry = 0.f;
    for (int c = 0; c < NC; c++) {
        int idx = (b * NC + c) * D + d;
        Cin[idx] = carry;
        carry = fmaf(Agg[idx], carry, Sgg[idx]);
    }
}

// ---------------- scan pass 3: redo local scan with carry, fuse hs2 = out*gate + residual ----------------
__global__ void __launch_bounds__(256) scan3_kernel(const float* __restrict__ a,
                                                    const float* __restrict__ s,
                                                    const float* __restrict__ Cin,
                                                    const float* __restrict__ gate,
                                                    const float* __restrict__ resid,
                                                    float* __restrict__ hs2) {
    int g = blockIdx.x * 256 + threadIdx.x;      // B*NC*D threads
    int d = g & (D - 1);
    int chunk = (g >> 10) & (NC - 1);
    int b = g >> 14;
    size_t base = ((size_t)b * L + (size_t)chunk * CL) * D + d;
    float carry = Cin[g];
    for (int t = 0; t < CL; t++) {
        size_t idx = base + (size_t)t * D;
        carry = fmaf(a[idx], carry, s[idx]);
        hs2[idx] = fmaf(carry, gate[idx], resid[idx]);
    }
}

// ---------------- launch ----------------
extern "C" void kernel_launch(void* const* d_in, const int* in_sizes, int n_in,
                              void* d_out, int out_size) {
    const float* hidden    = (const float*)d_in[0];
    const float* alpha     = (const float*)d_in[1];
    const float* fc_w      = (const float*)d_in[2];
    const float* fc_b      = (const float*)d_in[3];
    const float* fc_r_w    = (const float*)d_in[4];
    const float* fc_r_b    = (const float*)d_in[5];
    const float* fc_i_w    = (const float*)d_in[6];
    const float* fc_i_b    = (const float*)d_in[7];
    const float* fc_gate_w = (const float*)d_in[8];
    const float* fc_gate_b = (const float*)d_in[9];
    const float* norm_w    = (const float*)d_in[10];
    const float* norm2_w   = (const float*)d_in[11];
    const float* mlp_gate_w= (const float*)d_in[12];
    const float* mlp_gate_b= (const float*)d_in[13];
    const float* mlp_fc_w  = (const float*)d_in[14];
    const float* mlp_fc_b  = (const float*)d_in[15];
    const float* out_w     = (const float*)d_in[16];
    const float* out_b     = (const float*)d_in[17];
    float* out = (float*)d_out;

    float *p_h, *p_gate, *p_hs, *p_r, *p_i, *p_hs2, *p_g2, *p_f2, *p_Agg, *p_Sgg, *p_Cin;
    cudaGetSymbolAddress((void**)&p_h,   g_h);
    cudaGetSymbolAddress((void**)&p_gate,g_gate);
    cudaGetSymbolAddress((void**)&p_hs,  g_hs);
    cudaGetSymbolAddress((void**)&p_r,   g_r);
    cudaGetSymbolAddress((void**)&p_i,   g_i);
    cudaGetSymbolAddress((void**)&p_hs2, g_hs2);
    cudaGetSymbolAddress((void**)&p_g2,  g_g2);
    cudaGetSymbolAddress((void**)&p_f2,  g_f2);
    cudaGetSymbolAddress((void**)&p_Agg, g_Agg);
    cudaGetSymbolAddress((void**)&p_Sgg, g_Sgg);
    cudaGetSymbolAddress((void**)&p_Cin, g_Cin);

    // 1) rmsnorm1
    rmsnorm_kernel<<<N, 256>>>(hidden, norm_w, p_h);

    // 2) first-layer GEMMs (M=N tokens, O=D, K=D)
    dim3 g1(D/128, N/128);
    gemm_kernel<EPI_GELU><<<g1, 256>>>(p_h, fc_gate_w, fc_gate_b, nullptr, p_gate, N, D, D);
    gemm_kernel<EPI_NONE><<<g1, 256>>>(p_h, fc_w,      fc_b,      nullptr, p_hs,   N, D, D);
    gemm_kernel<EPI_SIG ><<<g1, 256>>>(p_h, fc_r_w,    fc_r_b,    nullptr, p_r,    N, D, D);
    gemm_kernel<EPI_SIG ><<<g1, 256>>>(p_h, fc_i_w,    fc_i_b,    nullptr, p_i,    N, D, D);

    // 3) a,s (in place over r,i buffers)
    as_kernel<<<(int)(ND/256), 256>>>(p_hs, p_r, p_i, alpha, p_r, p_i);

    // 4) chunked linear recurrence
    scan1_kernel<<<(B*NC*D)/256, 256>>>(p_r, p_i, p_Agg, p_Sgg);
    scan2_kernel<<<(B*D)/256, 256>>>(p_Agg, p_Sgg, p_Cin);
    scan3_kernel<<<(B*NC*D)/256, 256>>>(p_r, p_i, p_Cin, p_gate, hidden, p_hs2);

    // 5) rmsnorm2 (reuse g_h)
    rmsnorm_kernel<<<N, 256>>>(p_hs2, norm2_w, p_h);

    // 6) MLP GEMMs (O = 3D)
    dim3 g2(3*D/128, N/128);
    gemm_kernel<EPI_GELU><<<g2, 256>>>(p_h, mlp_gate_w, mlp_gate_b, nullptr, p_g2, N, 3*D, D);
    gemm_kernel<EPI_MUL ><<<g2, 256>>>(p_h, mlp_fc_w,   mlp_fc_b,   p_g2,    p_f2, N, 3*D, D);

    // 7) output projection + residual (K = 3D)
    gemm_kernel<EPI_ADD><<<g1, 256>>>(p_f2, out_w, out_b, p_hs2, out, N, D, 3*D);
}

// round 3
// speedup vs baseline: 3.1625x; 3.1625x over previous
#include <cuda_runtime.h>
#include <cuda_bf16.h>
#include <math.h>
#include <stdint.h>

#define D 1024
#define B 16
#define L 2048
#define N (B*L)              // 32768 tokens
#define NC 16                // scan chunks
#define CL (L/NC)            // 128

// ---- mma.sync GEMM tile config ----
#define BM 128
#define BN 256
#define BK 64                // bf16 elems per chunk -> 128B rows (SW128 swizzle)
#define S_AHI 0
#define S_ALO 16384
#define S_BHI 32768
#define S_BLO 65536
#define STAGE 98304          // 96KB per stage
#define SMEM_GEMM (2*STAGE)  // 192KB

// ---------------- scratch (static __device__, no allocations) ----------------
#define MW 1048576
__device__ float g_gate[(size_t)N*D];
__device__ float g_hs[(size_t)N*D];
__device__ float g_r[(size_t)N*D];
__device__ float g_i[(size_t)N*D];
__device__ float g_hs2[(size_t)N*D];
__device__ float g_g2[(size_t)N*3*D];
__device__ float g_Agg[B*NC*D];
__device__ float g_Sgg[B*NC*D];
__device__ float g_Cin[B*NC*D];
__device__ __nv_bfloat16 g_hhi[(size_t)N*D];
__device__ __nv_bfloat16 g_hlo[(size_t)N*D];
__device__ __nv_bfloat16 g_f2hi[(size_t)N*3*D];
__device__ __nv_bfloat16 g_f2lo[(size_t)N*3*D];
__device__ __nv_bfloat16 g_whi[(size_t)13*MW];
__device__ __nv_bfloat16 g_wlo[(size_t)13*MW];

// ---------------- PTX helpers (all sm_80+ portable) ----------------
__device__ __forceinline__ uint32_t smem_u32(const void* p) {
    uint32_t a;
    asm("{ .reg .u64 t; cvta.to.shared.u64 t, %1; cvt.u32.u64 %0, t; }" : "=r"(a) : "l"(p));
    return a;
}
__device__ __forceinline__ void cp16(uint32_t dst, const void* src) {
    asm volatile("cp.async.cg.shared.global [%0], [%1], 16;" :: "r"(dst), "l"(src));
}
#define CP_COMMIT() asm volatile("cp.async.commit_group;" ::: "memory")
#define CP_WAIT1()  asm volatile("cp.async.wait_group 1;"  ::: "memory")

__device__ __forceinline__ void ldsm4(uint32_t* r, uint32_t addr) {
    asm volatile("ldmatrix.sync.aligned.m8n8.x4.shared.b16 {%0,%1,%2,%3}, [%4];"
                 : "=r"(r[0]), "=r"(r[1]), "=r"(r[2]), "=r"(r[3]) : "r"(addr));
}
__device__ __forceinline__ void mma16816(float* d, const uint32_t* a, const uint32_t* b) {
    asm volatile("mma.sync.aligned.m16n8k16.row.col.f32.bf16.bf16.f32 "
                 "{%0,%1,%2,%3}, {%4,%5,%6,%7}, {%8,%9}, {%0,%1,%2,%3};"
                 : "+f"(d[0]), "+f"(d[1]), "+f"(d[2]), "+f"(d[3])
                 : "r"(a[0]), "r"(a[1]), "r"(a[2]), "r"(a[3]), "r"(b[0]), "r"(b[1]));
}

__device__ __forceinline__ float gelu_exact(float v) {
    return 0.5f * v * (1.0f + erff(v * 0.70710678118654752f));
}
__device__ __forceinline__ float sigmoid_f(float v) {
    return 1.0f / (1.0f + expf(-v));
}
__device__ __forceinline__ void split_one(float x, __nv_bfloat16& h, __nv_bfloat16& l) {
    h = __float2bfloat16(x);
    l = __float2bfloat16(x - __bfloat162float(h));
}

#define EPI_NONE 0
#define EPI_GELU 1
#define EPI_SIG  2
#define EPI_MUL  3
#define EPI_ADD  4

// ---------------- smem chunk loader (SW128 swizzle, cp.async 16B) ----------------
__device__ __forceinline__ void load_chunk(
    const __nv_bfloat16* __restrict__ Ahi, const __nv_bfloat16* __restrict__ Alo,
    const __nv_bfloat16* __restrict__ Bhi, const __nv_bfloat16* __restrict__ Blo,
    int K, int m0, int n0, int kc, uint32_t sb, int tid)
{
    #pragma unroll
    for (int it = 0; it < 4; it++) {              // A: 128 rows x 8 granules
        int g = tid + it * 256;
        int r = g >> 3, c = g & 7;
        uint32_t sw = (uint32_t)(r * 128) + (uint32_t)((c ^ (r & 7)) << 4);
        size_t e = (size_t)(m0 + r) * K + kc + c * 8;
        cp16(sb + S_AHI + sw, Ahi + e);
        cp16(sb + S_ALO + sw, Alo + e);
    }
    #pragma unroll
    for (int it = 0; it < 8; it++) {              // B: 256 rows x 8 granules
        int g = tid + it * 256;
        int r = g >> 3, c = g & 7;
        uint32_t sw = (uint32_t)(r * 128) + (uint32_t)((c ^ (r & 7)) << 4);
        size_t e = (size_t)(n0 + r) * K + kc + c * 8;
        cp16(sb + S_BHI + sw, Bhi + e);
        cp16(sb + S_BLO + sw, Blo + e);
    }
}

// ---------------- mma.sync GEMM ----------------
// C[M,O] = A[M,K] * W[O,K]^T + bias, fp32-accurate via bf16 hi/lo 3-term split.
// 8 warps as 2(M) x 4(N), warp tile 64x64.
template<int EPI>
__global__ void __launch_bounds__(256, 1) gemm_mma(
    const __nv_bfloat16* __restrict__ Ahi, const __nv_bfloat16* __restrict__ Alo,
    const __nv_bfloat16* __restrict__ Bhi, const __nv_bfloat16* __restrict__ Blo,
    const float* __restrict__ bias, const float* __restrict__ aux,
    float* __restrict__ Co, __nv_bfloat16* __restrict__ Chi, __nv_bfloat16* __restrict__ Clo,
    int K)
{
    extern __shared__ __align__(1024) char smem[];
    const uint32_t sb0 = smem_u32(smem);
    const int tid = threadIdx.x;
    const int lane = tid & 31, wid = tid >> 5;
    const int m0 = blockIdx.y * BM, n0 = blockIdx.x * BN;
    const int O = gridDim.x * BN;
    const int wm = (wid & 1) * 64, wn = (wid >> 1) * 64;

    float acc[4][8][4];
    #pragma unroll
    for (int i = 0; i < 4; i++)
        #pragma unroll
        for (int j = 0; j < 8; j++)
            #pragma unroll
            for (int q = 0; q < 4; q++) acc[i][j][q] = 0.f;

    const int NCH = K / BK;
    load_chunk(Ahi, Alo, Bhi, Blo, K, m0, n0, 0, sb0, tid);
    CP_COMMIT();
    load_chunk(Ahi, Alo, Bhi, Blo, K, m0, n0, BK, sb0 + STAGE, tid);
    CP_COMMIT();

    // ldmatrix lane geometry
    const int arow = wm + (lane & 15);            // + mi*16
    const int ag   = lane >> 4;                   // k-half granule
    const int brow = wn + ((lane >> 4) << 3) + (lane & 7);   // + np*16
    const int bg   = (lane >> 3) & 1;

    for (int c = 0; c < NCH; c++) {
        CP_WAIT1();
        __syncthreads();
        const uint32_t sb = sb0 + (uint32_t)(c & 1) * STAGE;
        #pragma unroll
        for (int ks = 0; ks < 4; ks++) {
            uint32_t a[4][4], bh[8][2], bl[8][2];
            #pragma unroll
            for (int mi = 0; mi < 4; mi++) {
                int r = arow + mi * 16;
                uint32_t ad = sb + S_AHI + (uint32_t)(r * 128)
                            + (uint32_t)((((ks * 2 + ag)) ^ (r & 7)) << 4);
                ldsm4(a[mi], ad);
            }
            #pragma unroll
            for (int np = 0; np < 4; np++) {
                int r = brow + np * 16;
                uint32_t off = (uint32_t)(r * 128)
                             + (uint32_t)((((ks * 2 + bg)) ^ (r & 7)) << 4);
                uint32_t t[4];
                ldsm4(t, sb + S_BHI + off);
                bh[2*np][0] = t[0]; bh[2*np][1] = t[1];
                bh[2*np+1][0] = t[2]; bh[2*np+1][1] = t[3];
                ldsm4(t, sb + S_BLO + off);
                bl[2*np][0] = t[0]; bl[2*np][1] = t[1];
                bl[2*np+1][0] = t[2]; bl[2*np+1][1] = t[3];
            }
            #pragma unroll
            for (int mi = 0; mi < 4; mi++)
                #pragma unroll
                for (int ni = 0; ni < 8; ni++)
                    mma16816(acc[mi][ni], a[mi], bh[ni]);
            #pragma unroll
            for (int mi = 0; mi < 4; mi++)
                #pragma unroll
                for (int ni = 0; ni < 8; ni++)
                    mma16816(acc[mi][ni], a[mi], bl[ni]);
            #pragma unroll
            for (int mi = 0; mi < 4; mi++) {      // reload a <- Alo (reuse regs)
                int r = arow + mi * 16;
                uint32_t ad = sb + S_ALO + (uint32_t)(r * 128)
                            + (uint32_t)((((ks * 2 + ag)) ^ (r & 7)) << 4);
                ldsm4(a[mi], ad);
            }
            #pragma unroll
            for (int mi = 0; mi < 4; mi++)
                #pragma unroll
                for (int ni = 0; ni < 8; ni++)
                    mma16816(acc[mi][ni], a[mi], bh[ni]);
        }
        __syncthreads();
        if (c + 2 < NCH)
            load_chunk(Ahi, Alo, Bhi, Blo, K, m0, n0, (c + 2) * BK, sb, tid);
        CP_COMMIT();
    }

    // ---- epilogue ----
    const int gr = lane >> 2;        // groupID -> row
    const int tg = lane & 3;         // -> col*2
    #pragma unroll
    for (int mi = 0; mi < 4; mi++) {
        #pragma unroll
        for (int ni = 0; ni < 8; ni++) {
            int r0 = m0 + wm + mi * 16 + gr;
            int cc = n0 + wn + ni * 8 + tg * 2;
            float b0 = bias[cc], b1 = bias[cc + 1];
            size_t o0 = (size_t)r0 * O + cc;
            size_t o8 = (size_t)(r0 + 8) * O + cc;
            float v0 = acc[mi][ni][0] + b0, v1 = acc[mi][ni][1] + b1;
            float v2 = acc[mi][ni][2] + b0, v3 = acc[mi][ni][3] + b1;
            if (EPI == EPI_GELU) {
                v0 = gelu_exact(v0); v1 = gelu_exact(v1);
                v2 = gelu_exact(v2); v3 = gelu_exact(v3);
            } else if (EPI == EPI_SIG) {
                v0 = sigmoid_f(v0); v1 = sigmoid_f(v1);
                v2 = sigmoid_f(v2); v3 = sigmoid_f(v3);
            } else if (EPI == EPI_MUL) {
                float2 x0 = *(const float2*)(aux + o0);
                float2 x8 = *(const float2*)(aux + o8);
                v0 *= x0.x; v1 *= x0.y; v2 *= x8.x; v3 *= x8.y;
            } else if (EPI == EPI_ADD) {
                float2 x0 = *(const float2*)(aux + o0);
                float2 x8 = *(const float2*)(aux + o8);
                v0 += x0.x; v1 += x0.y; v2 += x8.x; v3 += x8.y;
            }
            if (EPI == EPI_MUL) {
                __nv_bfloat16 h0, l0, h1, l1;
                split_one(v0, h0, l0); split_one(v1, h1, l1);
                __nv_bfloat162 hh; hh.x = h0; hh.y = h1;
                __nv_bfloat162 ll; ll.x = l0; ll.y = l1;
                *(__nv_bfloat162*)(Chi + o0) = hh;
                *(__nv_bfloat162*)(Clo + o0) = ll;
                split_one(v2, h0, l0); split_one(v3, h1, l1);
                hh.x = h0; hh.y = h1; ll.x = l0; ll.y = l1;
                *(__nv_bfloat162*)(Chi + o8) = hh;
                *(__nv_bfloat162*)(Clo + o8) = ll;
            } else {
                *(float2*)(Co + o0) = make_float2(v0, v1);
                *(float2*)(Co + o8) = make_float2(v2, v3);
            }
        }
    }
}

// ---------------- weight split: fp32 -> bf16 hi/lo ----------------
__global__ void __launch_bounds__(256) split4_kernel(const float* __restrict__ src,
                                                     __nv_bfloat16* __restrict__ hi,
                                                     __nv_bfloat16* __restrict__ lo) {
    int idx = blockIdx.x * 256 + threadIdx.x;
    float4 v = ((const float4*)src)[idx];
    __nv_bfloat16 h0, l0, h1, l1, h2, l2, h3, l3;
    split_one(v.x, h0, l0); split_one(v.y, h1, l1);
    split_one(v.z, h2, l2); split_one(v.w, h3, l3);
    __nv_bfloat162 a; a.x = h0; a.y = h1;
    __nv_bfloat162 b; b.x = h2; b.y = h3;
    __nv_bfloat162 c; c.x = l0; c.y = l1;
    __nv_bfloat162 d; d.x = l2; d.y = l3;
    ((__nv_bfloat162*)hi)[idx * 2] = a; ((__nv_bfloat162*)hi)[idx * 2 + 1] = b;
    ((__nv_bfloat162*)lo)[idx * 2] = c; ((__nv_bfloat162*)lo)[idx * 2 + 1] = d;
}

// ---------------- rmsnorm -> bf16 hi/lo ----------------
__global__ void __launch_bounds__(256) rmsnorm_split_kernel(const float* __restrict__ x,
                                                            const float* __restrict__ w,
                                                            __nv_bfloat16* __restrict__ yhi,
                                                            __nv_bfloat16* __restrict__ ylo) {
    int row = blockIdx.x;
    int t = threadIdx.x;
    const float4* xr = (const float4*)(x + (size_t)row * D);
    float4 xv = xr[t];
    float ss = xv.x * xv.x + xv.y * xv.y + xv.z * xv.z + xv.w * xv.w;
    #pragma unroll
    for (int o = 16; o > 0; o >>= 1) ss += __shfl_xor_sync(0xffffffffu, ss, o);
    __shared__ float red[8];
    if ((t & 31) == 0) red[t >> 5] = ss;
    __syncthreads();
    if (t < 32) {
        float v = (t < 8) ? red[t] : 0.f;
        #pragma unroll
        for (int o = 4; o > 0; o >>= 1) v += __shfl_xor_sync(0xffffffffu, v, o);
        if (t == 0) red[0] = v;
    }
    __syncthreads();
    float scale = rsqrtf(red[0] * (1.0f / (float)D) + 1e-6f);
    float4 wv = ((const float4*)w)[t];
    float o0 = xv.x * scale * wv.x, o1 = xv.y * scale * wv.y;
    float o2 = xv.z * scale * wv.z, o3 = xv.w * scale * wv.w;
    __nv_bfloat16 h0, l0, h1, l1, h2, l2, h3, l3;
    split_one(o0, h0, l0); split_one(o1, h1, l1);
    split_one(o2, h2, l2); split_one(o3, h3, l3);
    size_t base2 = (size_t)row * (D / 2) + t * 2;
    __nv_bfloat162 a; a.x = h0; a.y = h1;
    __nv_bfloat162 b; b.x = h2; b.y = h3;
    __nv_bfloat162 c; c.x = l0; c.y = l1;
    __nv_bfloat162 d; d.x = l2; d.y = l3;
    ((__nv_bfloat162*)yhi)[base2] = a; ((__nv_bfloat162*)yhi)[base2 + 1] = b;
    ((__nv_bfloat162*)ylo)[base2] = c; ((__nv_bfloat162*)ylo)[base2 + 1] = d;
}

// ---------------- elementwise a,s ----------------
__global__ void __launch_bounds__(256) as_kernel(const float* __restrict__ hs,
                                                 const float* __restrict__ r,
                                                 const float* __restrict__ iv,
                                                 const float* __restrict__ alpha,
                                                 float* __restrict__ a_out,
                                                 float* __restrict__ s_out) {
    int idx = blockIdx.x * 256 + threadIdx.x;
    int d = idx & (D - 1);
    float sp = log1pf(expf(alpha[d]));
    float a = expf(-8.0f * sp * r[idx]);
    float s = sqrtf(fmaxf(1.0f - a * a, 0.0f)) * hs[idx] * iv[idx];
    a_out[idx] = a;
    s_out[idx] = s;
}

// ---------------- chunked scan ----------------
__global__ void __launch_bounds__(256) scan1_kernel(const float* __restrict__ a,
                                                    const float* __restrict__ s,
                                                    float* __restrict__ Agg,
                                                    float* __restrict__ Sgg) {
    int g = blockIdx.x * 256 + threadIdx.x;
    int d = g & (D - 1);
    int chunk = (g >> 10) & (NC - 1);
    int b = g >> 14;
    size_t base = ((size_t)b * L + (size_t)chunk * CL) * D + d;
    float Ap = 1.f, S = 0.f;
    for (int t = 0; t < CL; t++) {
        float at = a[base + (size_t)t * D];
        float st = s[base + (size_t)t * D];
        S = fmaf(at, S, st);
        Ap *= at;
    }
    Agg[g] = Ap;
    Sgg[g] = S;
}

__global__ void __launch_bounds__(256) scan2_kernel(const float* __restrict__ Agg,
                                                    const float* __restrict__ Sgg,
                                                    float* __restrict__ Cin) {
    int g = blockIdx.x * 256 + threadIdx.x;
    int d = g & (D - 1);
    int b = g >> 10;
    float carry = 0.f;
    for (int c = 0; c < NC; c++) {
        int idx = (b * NC + c) * D + d;
        Cin[idx] = carry;
        carry = fmaf(Agg[idx], carry, Sgg[idx]);
    }
}

__global__ void __launch_bounds__(256) scan3_kernel(const float* __restrict__ a,
                                                    const float* __restrict__ s,
                                                    const float* __restrict__ Cin,
                                                    const float* __restrict__ gate,
                                                    const float* __restrict__ resid,
                                                    float* __restrict__ hs2) {
    int g = blockIdx.x * 256 + threadIdx.x;
    int d = g & (D - 1);
    int chunk = (g >> 10) & (NC - 1);
    int b = g >> 14;
    size_t base = ((size_t)b * L + (size_t)chunk * CL) * D + d;
    float carry = Cin[g];
    for (int t = 0; t < CL; t++) {
        size_t idx = base + (size_t)t * D;
        carry = fmaf(a[idx], carry, s[idx]);
        hs2[idx] = fmaf(carry, gate[idx], resid[idx]);
    }
}

// ---------------- launch ----------------
extern "C" void kernel_launch(void* const* d_in, const int* in_sizes, int n_in,
                              void* d_out, int out_size) {
    const float* hidden    = (const float*)d_in[0];
    const float* alpha     = (const float*)d_in[1];
    const float* fc_w      = (const float*)d_in[2];
    const float* fc_b      = (const float*)d_in[3];
    const float* fc_r_w    = (const float*)d_in[4];
    const float* fc_r_b    = (const float*)d_in[5];
    const float* fc_i_w    = (const float*)d_in[6];
    const float* fc_i_b    = (const float*)d_in[7];
    const float* fc_gate_w = (const float*)d_in[8];
    const float* fc_gate_b = (const float*)d_in[9];
    const float* norm_w    = (const float*)d_in[10];
    const float* norm2_w   = (const float*)d_in[11];
    const float* mlp_gate_w= (const float*)d_in[12];
    const float* mlp_gate_b= (const float*)d_in[13];
    const float* mlp_fc_w  = (const float*)d_in[14];
    const float* mlp_fc_b  = (const float*)d_in[15];
    const float* out_w     = (const float*)d_in[16];
    const float* out_b     = (const float*)d_in[17];
    float* out = (float*)d_out;

    float *p_gate, *p_hs, *p_r, *p_i, *p_hs2, *p_g2, *p_Agg, *p_Sgg, *p_Cin;
    __nv_bfloat16 *p_hhi, *p_hlo, *p_f2hi, *p_f2lo, *p_whi, *p_wlo;
    cudaGetSymbolAddress((void**)&p_gate, g_gate);
    cudaGetSymbolAddress((void**)&p_hs,   g_hs);
    cudaGetSymbolAddress((void**)&p_r,    g_r);
    cudaGetSymbolAddress((void**)&p_i,    g_i);
    cudaGetSymbolAddress((void**)&p_hs2,  g_hs2);
    cudaGetSymbolAddress((void**)&p_g2,   g_g2);
    cudaGetSymbolAddress((void**)&p_Agg,  g_Agg);
    cudaGetSymbolAddress((void**)&p_Sgg,  g_Sgg);
    cudaGetSymbolAddress((void**)&p_Cin,  g_Cin);
    cudaGetSymbolAddress((void**)&p_hhi,  g_hhi);
    cudaGetSymbolAddress((void**)&p_hlo,  g_hlo);
    cudaGetSymbolAddress((void**)&p_f2hi, g_f2hi);
    cudaGetSymbolAddress((void**)&p_f2lo, g_f2lo);
    cudaGetSymbolAddress((void**)&p_whi,  g_whi);
    cudaGetSymbolAddress((void**)&p_wlo,  g_wlo);

    cudaFuncSetAttribute(gemm_mma<EPI_NONE>, cudaFuncAttributeMaxDynamicSharedMemorySize, SMEM_GEMM);
    cudaFuncSetAttribute(gemm_mma<EPI_GELU>, cudaFuncAttributeMaxDynamicSharedMemorySize, SMEM_GEMM);
    cudaFuncSetAttribute(gemm_mma<EPI_SIG >, cudaFuncAttributeMaxDynamicSharedMemorySize, SMEM_GEMM);
    cudaFuncSetAttribute(gemm_mma<EPI_MUL >, cudaFuncAttributeMaxDynamicSharedMemorySize, SMEM_GEMM);
    cudaFuncSetAttribute(gemm_mma<EPI_ADD >, cudaFuncAttributeMaxDynamicSharedMemorySize, SMEM_GEMM);

    // weight arena offsets (elems)
    const size_t O_FC = 0, O_FCR = 1 * MW, O_FCI = 2 * MW, O_FCG = 3 * MW;
    const size_t O_MG = 4 * MW, O_MF = 7 * MW, O_OW = 10 * MW;

    // 0) split weights fp32 -> bf16 hi/lo
    split4_kernel<<<MW / 1024, 256>>>(fc_w,       p_whi + O_FC,  p_wlo + O_FC);
    split4_kernel<<<MW / 1024, 256>>>(fc_r_w,     p_whi + O_FCR, p_wlo + O_FCR);
    split4_kernel<<<MW / 1024, 256>>>(fc_i_w,     p_whi + O_FCI, p_wlo + O_FCI);
    split4_kernel<<<MW / 1024, 256>>>(fc_gate_w,  p_whi + O_FCG, p_wlo + O_FCG);
    split4_kernel<<<3 * MW / 1024, 256>>>(mlp_gate_w, p_whi + O_MG, p_wlo + O_MG);
    split4_kernel<<<3 * MW / 1024, 256>>>(mlp_fc_w,   p_whi + O_MF, p_wlo + O_MF);
    split4_kernel<<<3 * MW / 1024, 256>>>(out_w,      p_whi + O_OW, p_wlo + O_OW);

    // 1) rmsnorm1 -> h hi/lo
    rmsnorm_split_kernel<<<N, 256>>>(hidden, norm_w, p_hhi, p_hlo);

    // 2) first-layer GEMMs (O = D)
    dim3 g1(D / BN, N / BM);                 // (4, 256)
    gemm_mma<EPI_GELU><<<g1, 256, SMEM_GEMM>>>(p_hhi, p_hlo, p_whi + O_FCG, p_wlo + O_FCG, fc_gate_b, nullptr, p_gate, nullptr, nullptr, D);
    gemm_mma<EPI_NONE><<<g1, 256, SMEM_GEMM>>>(p_hhi, p_hlo, p_whi + O_FC,  p_wlo + O_FC,  fc_b,      nullptr, p_hs,   nullptr, nullptr, D);
    gemm_mma<EPI_SIG ><<<g1, 256, SMEM_GEMM>>>(p_hhi, p_hlo, p_whi + O_FCR, p_wlo + O_FCR, fc_r_b,    nullptr, p_r,    nullptr, nullptr, D);
    gemm_mma<EPI_SIG ><<<g1, 256, SMEM_GEMM>>>(p_hhi, p_hlo, p_whi + O_FCI, p_wlo + O_FCI, fc_i_b,    nullptr, p_i,    nullptr, nullptr, D);

    // 3) a,s elementwise (in-place over r,i)
    as_kernel<<<(int)(((size_t)N * D) / 256), 256>>>(p_hs, p_r, p_i, alpha, p_r, p_i);

    // 4) chunked linear recurrence + fused gate/residual
    scan1_kernel<<<(B * NC * D) / 256, 256>>>(p_r, p_i, p_Agg, p_Sgg);
    scan2_kernel<<<(B * D) / 256, 256>>>(p_Agg, p_Sgg, p_Cin);
    scan3_kernel<<<(B * NC * D) / 256, 256>>>(p_r, p_i, p_Cin, p_gate, hidden, p_hs2);

    // 5) rmsnorm2 -> h hi/lo (reuse buffers)
    rmsnorm_split_kernel<<<N, 256>>>(p_hs2, norm2_w, p_hhi, p_hlo);

    // 6) MLP GEMMs (O = 3D)
    dim3 g2(3 * D / BN, N / BM);             // (12, 256)
    gemm_mma<EPI_GELU><<<g2, 256, SMEM_GEMM>>>(p_hhi, p_hlo, p_whi + O_MG, p_wlo + O_MG, mlp_gate_b, nullptr, p_g2, nullptr, nullptr, D);
    gemm_mma<EPI_MUL ><<<g2, 256, SMEM_GEMM>>>(p_hhi, p_hlo, p_whi + O_MF, p_wlo + O_MF, mlp_fc_b,   p_g2,    nullptr, p_f2hi, p_f2lo, D);

    // 7) output projection + residual (K = 3D)
    gemm_mma<EPI_ADD><<<g1, 256, SMEM_GEMM>>>(p_f2hi, p_f2lo, p_whi + O_OW, p_wlo + O_OW, out_b, p_hs2, out, nullptr, nullptr, 3 * D);
}

// round 4
// speedup vs baseline: 3.1907x; 1.0089x over previous
#include <cuda_runtime.h>
#include <cuda_bf16.h>
#include <math.h>
#include <stdint.h>

#define D 1024
#define B 16
#define L 2048
#define N (B*L)              // 32768 tokens
#define NC 16                // scan chunks
#define CL (L/NC)            // 128

// ---- mma.sync GEMM tile config ----
#define BM 128
#define BN 256
#define BK 64                // bf16 elems per chunk -> 128B rows (SW128 swizzle)
#define S_AHI 0
#define S_ALO 16384
#define S_BHI 32768
#define S_BLO 65536
#define STAGE 98304          // 96KB per stage
#define SMEM_GEMM (2*STAGE)  // 192KB

// ---------------- scratch (static __device__, no allocations) ----------------
#define MW 1048576
__device__ float g_gate[(size_t)N*D];
__device__ float g_hs[(size_t)N*D];
__device__ float g_r[(size_t)N*D];
__device__ float g_i[(size_t)N*D];
__device__ float g_hs2[(size_t)N*D];
__device__ float g_g2[(size_t)N*3*D];
__device__ float g_Agg[B*NC*D];
__device__ float g_Sgg[B*NC*D];
__device__ float g_Cin[B*NC*D];
__device__ __nv_bfloat16 g_hhi[(size_t)N*D];
__device__ __nv_bfloat16 g_hlo[(size_t)N*D];
__device__ __nv_bfloat16 g_f2hi[(size_t)N*3*D];
__device__ __nv_bfloat16 g_f2lo[(size_t)N*3*D];
__device__ __nv_bfloat16 g_whi[(size_t)13*MW];
__device__ __nv_bfloat16 g_wlo[(size_t)13*MW];

// ---------------- PTX helpers (all sm_80+ portable) ----------------
__device__ __forceinline__ uint32_t smem_u32(const void* p) {
    uint32_t a;
    asm("{ .reg .u64 t; cvta.to.shared.u64 t, %1; cvt.u32.u64 %0, t; }" : "=r"(a) : "l"(p));
    return a;
}
__device__ __forceinline__ void cp16(uint32_t dst, const void* src) {
    asm volatile("cp.async.cg.shared.global [%0], [%1], 16;" :: "r"(dst), "l"(src));
}
#define CP_COMMIT() asm volatile("cp.async.commit_group;" ::: "memory")
#define CP_WAIT1()  asm volatile("cp.async.wait_group 1;"  ::: "memory")

__device__ __forceinline__ void ldsm4(uint32_t* r, uint32_t addr) {
    asm volatile("ldmatrix.sync.aligned.m8n8.x4.shared.b16 {%0,%1,%2,%3}, [%4];"
                 : "=r"(r[0]), "=r"(r[1]), "=r"(r[2]), "=r"(r[3]) : "r"(addr));
}
__device__ __forceinline__ void mma16816(float* d, const uint32_t* a, const uint32_t* b) {
    asm volatile("mma.sync.aligned.m16n8k16.row.col.f32.bf16.bf16.f32 "
                 "{%0,%1,%2,%3}, {%4,%5,%6,%7}, {%8,%9}, {%0,%1,%2,%3};"
                 : "+f"(d[0]), "+f"(d[1]), "+f"(d[2]), "+f"(d[3])
                 : "r"(a[0]), "r"(a[1]), "r"(a[2]), "r"(a[3]), "r"(b[0]), "r"(b[1]));
}

__device__ __forceinline__ float gelu_exact(float v) {
    return 0.5f * v * (1.0f + erff(v * 0.70710678118654752f));
}
__device__ __forceinline__ float sigmoid_f(float v) {
    return 1.0f / (1.0f + expf(-v));
}
__device__ __forceinline__ void split_one(float x, __nv_bfloat16& h, __nv_bfloat16& l) {
    h = __float2bfloat16(x);
    l = __float2bfloat16(x - __bfloat162float(h));
}

#define EPI_NONE 0
#define EPI_GELU 1
#define EPI_SIG  2
#define EPI_MUL  3
#define EPI_ADD  4

// ---------------- smem chunk loader (SW128 swizzle, cp.async 16B) ----------------
__device__ __forceinline__ void load_chunk(
    const __nv_bfloat16* __restrict__ Ahi, const __nv_bfloat16* __restrict__ Alo,
    const __nv_bfloat16* __restrict__ Bhi, const __nv_bfloat16* __restrict__ Blo,
    int K, int m0, int n0, int kc, uint32_t sb, int tid)
{
    #pragma unroll
    for (int it = 0; it < 4; it++) {              // A: 128 rows x 8 granules
        int g = tid + it * 256;
        int r = g >> 3, c = g & 7;
        uint32_t sw = (uint32_t)(r * 128) + (uint32_t)((c ^ (r & 7)) << 4);
        size_t e = (size_t)(m0 + r) * K + kc + c * 8;
        cp16(sb + S_AHI + sw, Ahi + e);
        cp16(sb + S_ALO + sw, Alo + e);
    }
    #pragma unroll
    for (int it = 0; it < 8; it++) {              // B: 256 rows x 8 granules
        int g = tid + it * 256;
        int r = g >> 3, c = g & 7;
        uint32_t sw = (uint32_t)(r * 128) + (uint32_t)((c ^ (r & 7)) << 4);
        size_t e = (size_t)(n0 + r) * K + kc + c * 8;
        cp16(sb + S_BHI + sw, Bhi + e);
        cp16(sb + S_BLO + sw, Blo + e);
    }
}

// ---------------- mma.sync GEMM ----------------
// C[M,O] = A[M,K] * W[O,K]^T + bias, fp32-accurate via bf16 hi/lo 3-term split.
// 8 warps as 2(M) x 4(N), warp tile 64x64.
template<int EPI>
__global__ void __launch_bounds__(256, 1) gemm_mma(
    const __nv_bfloat16* __restrict__ Ahi, const __nv_bfloat16* __restrict__ Alo,
    const __nv_bfloat16* __restrict__ Bhi, const __nv_bfloat16* __restrict__ Blo,
    const float* __restrict__ bias, const float* __restrict__ aux,
    float* __restrict__ Co, __nv_bfloat16* __restrict__ Chi, __nv_bfloat16* __restrict__ Clo,
    int K)
{
    extern __shared__ __align__(1024) char smem[];
    const uint32_t sb0 = smem_u32(smem);
    const int tid = threadIdx.x;
    const int lane = tid & 31, wid = tid >> 5;
    const int m0 = blockIdx.y * BM, n0 = blockIdx.x * BN;
    const int O = gridDim.x * BN;
    const int wm = (wid & 1) * 64, wn = (wid >> 1) * 64;

    float acc[4][8][4];
    #pragma unroll
    for (int i = 0; i < 4; i++)
        #pragma unroll
        for (int j = 0; j < 8; j++)
            #pragma unroll
            for (int q = 0; q < 4; q++) acc[i][j][q] = 0.f;

    const int NCH = K / BK;
    load_chunk(Ahi, Alo, Bhi, Blo, K, m0, n0, 0, sb0, tid);
    CP_COMMIT();
    load_chunk(Ahi, Alo, Bhi, Blo, K, m0, n0, BK, sb0 + STAGE, tid);
    CP_COMMIT();

    // ldmatrix lane geometry
    const int arow = wm + (lane & 15);            // + mi*16
    const int ag   = lane >> 4;                   // k-half granule
    const int brow = wn + ((lane >> 4) << 3) + (lane & 7);   // + np*16
    const int bg   = (lane >> 3) & 1;

    for (int c = 0; c < NCH; c++) {
        CP_WAIT1();
        __syncthreads();
        const uint32_t sb = sb0 + (uint32_t)(c & 1) * STAGE;
        #pragma unroll
        for (int ks = 0; ks < 4; ks++) {
            uint32_t a[4][4], bh[8][2], bl[8][2];
            #pragma unroll
            for (int mi = 0; mi < 4; mi++) {
                int r = arow + mi * 16;
                uint32_t ad = sb + S_AHI + (uint32_t)(r * 128)
                            + (uint32_t)((((ks * 2 + ag)) ^ (r & 7)) << 4);
                ldsm4(a[mi], ad);
            }
            #pragma unroll
            for (int np = 0; np < 4; np++) {
                int r = brow + np * 16;
                uint32_t off = (uint32_t)(r * 128)
                             + (uint32_t)((((ks * 2 + bg)) ^ (r & 7)) << 4);
                uint32_t t[4];
                ldsm4(t, sb + S_BHI + off);
                bh[2*np][0] = t[0]; bh[2*np][1] = t[1];
                bh[2*np+1][0] = t[2]; bh[2*np+1][1] = t[3];
                ldsm4(t, sb + S_BLO + off);
                bl[2*np][0] = t[0]; bl[2*np][1] = t[1];
                bl[2*np+1][0] = t[2]; bl[2*np+1][1] = t[3];
            }
            #pragma unroll
            for (int mi = 0; mi < 4; mi++)
                #pragma unroll
                for (int ni = 0; ni < 8; ni++)
                    mma16816(acc[mi][ni], a[mi], bh[ni]);
            #pragma unroll
            for (int mi = 0; mi < 4; mi++)
                #pragma unroll
                for (int ni = 0; ni < 8; ni++)
                    mma16816(acc[mi][ni], a[mi], bl[ni]);
            #pragma unroll
            for (int mi = 0; mi < 4; mi++) {      // reload a <- Alo (reuse regs)
                int r = arow + mi * 16;
                uint32_t ad = sb + S_ALO + (uint32_t)(r * 128)
                            + (uint32_t)((((ks * 2 + ag)) ^ (r & 7)) << 4);
                ldsm4(a[mi], ad);
            }
            #pragma unroll
            for (int mi = 0; mi < 4; mi++)
                #pragma unroll
                for (int ni = 0; ni < 8; ni++)
                    mma16816(acc[mi][ni], a[mi], bh[ni]);
        }
        __syncthreads();
        if (c + 2 < NCH)
            load_chunk(Ahi, Alo, Bhi, Blo, K, m0, n0, (c + 2) * BK, sb, tid);
        CP_COMMIT();
    }

    // ---- epilogue ----
    const int gr = lane >> 2;        // groupID -> row
    const int tg = lane & 3;         // -> col*2
    #pragma unroll
    for (int mi = 0; mi < 4; mi++) {
        #pragma unroll
        for (int ni = 0; ni < 8; ni++) {
            int r0 = m0 + wm + mi * 16 + gr;
            int cc = n0 + wn + ni * 8 + tg * 2;
            float b0 = bias[cc], b1 = bias[cc + 1];
            size_t o0 = (size_t)r0 * O + cc;
            size_t o8 = (size_t)(r0 + 8) * O + cc;
            float v0 = acc[mi][ni][0] + b0, v1 = acc[mi][ni][1] + b1;
            float v2 = acc[mi][ni][2] + b0, v3 = acc[mi][ni][3] + b1;
            if (EPI == EPI_GELU) {
                v0 = gelu_exact(v0); v1 = gelu_exact(v1);
                v2 = gelu_exact(v2); v3 = gelu_exact(v3);
            } else if (EPI == EPI_SIG) {
                v0 = sigmoid_f(v0); v1 = sigmoid_f(v1);
                v2 = sigmoid_f(v2); v3 = sigmoid_f(v3);
            } else if (EPI == EPI_MUL) {
                float2 x0 = *(const float2*)(aux + o0);
                float2 x8 = *(const float2*)(aux + o8);
                v0 *= x0.x; v1 *= x0.y; v2 *= x8.x; v3 *= x8.y;
            } else if (EPI == EPI_ADD) {
                float2 x0 = *(const float2*)(aux + o0);
                float2 x8 = *(const float2*)(aux + o8);
                v0 += x0.x; v1 += x0.y; v2 += x8.x; v3 += x8.y;
            }
            if (EPI == EPI_MUL) {
                __nv_bfloat16 h0, l0, h1, l1;
                split_one(v0, h0, l0); split_one(v1, h1, l1);
                __nv_bfloat162 hh; hh.x = h0; hh.y = h1;
                __nv_bfloat162 ll; ll.x = l0; ll.y = l1;
                *(__nv_bfloat162*)(Chi + o0) = hh;
                *(__nv_bfloat162*)(Clo + o0) = ll;
                split_one(v2, h0, l0); split_one(v3, h1, l1);
                hh.x = h0; hh.y = h1; ll.x = l0; ll.y = l1;
                *(__nv_bfloat162*)(Chi + o8) = hh;
                *(__nv_bfloat162*)(Clo + o8) = ll;
            } else {
                *(float2*)(Co + o0) = make_float2(v0, v1);
                *(float2*)(Co + o8) = make_float2(v2, v3);
            }
        }
    }
}

// ---------------- batched weight split: 4 small (D*D) sources in one launch ----------------
__global__ void __launch_bounds__(256) split_small4(const float* __restrict__ s0,
                                                    const float* __restrict__ s1,
                                                    const float* __restrict__ s2,
                                                    const float* __restrict__ s3,
                                                    __nv_bfloat16* __restrict__ hi,
                                                    __nv_bfloat16* __restrict__ lo) {
    const float* src = (blockIdx.y == 0) ? s0 : (blockIdx.y == 1) ? s1 : (blockIdx.y == 2) ? s2 : s3;
    size_t dst0 = (size_t)blockIdx.y * MW;
    int idx = blockIdx.x * 256 + threadIdx.x;
    float4 v = ((const float4*)src)[idx];
    __nv_bfloat16 h0, l0, h1, l1, h2, l2, h3, l3;
    split_one(v.x, h0, l0); split_one(v.y, h1, l1);
    split_one(v.z, h2, l2); split_one(v.w, h3, l3);
    __nv_bfloat162 a; a.x = h0; a.y = h1;
    __nv_bfloat162 b; b.x = h2; b.y = h3;
    __nv_bfloat162 c; c.x = l0; c.y = l1;
    __nv_bfloat162 d; d.x = l2; d.y = l3;
    __nv_bfloat162* ph = (__nv_bfloat162*)(hi + dst0);
    __nv_bfloat162* pl = (__nv_bfloat162*)(lo + dst0);
    ph[idx * 2] = a; ph[idx * 2 + 1] = b;
    pl[idx * 2] = c; pl[idx * 2 + 1] = d;
}

// ---------------- batched weight split: 3 big (3*D*D) sources in one launch ----------------
__global__ void __launch_bounds__(256) split_big3(const float* __restrict__ s0,
                                                  const float* __restrict__ s1,
                                                  const float* __restrict__ s2,
                                                  __nv_bfloat16* __restrict__ hi,
                                                  __nv_bfloat16* __restrict__ lo) {
    const float* src = (blockIdx.y == 0) ? s0 : (blockIdx.y == 1) ? s1 : s2;
    size_t dst0 = (size_t)(4 + 3 * blockIdx.y) * MW;
    int idx = blockIdx.x * 256 + threadIdx.x;
    float4 v = ((const float4*)src)[idx];
    __nv_bfloat16 h0, l0, h1, l1, h2, l2, h3, l3;
    split_one(v.x, h0, l0); split_one(v.y, h1, l1);
    split_one(v.z, h2, l2); split_one(v.w, h3, l3);
    __nv_bfloat162 a; a.x = h0; a.y = h1;
    __nv_bfloat162 b; b.x = h2; b.y = h3;
    __nv_bfloat162 c; c.x = l0; c.y = l1;
    __nv_bfloat162 d; d.x = l2; d.y = l3;
    __nv_bfloat162* ph = (__nv_bfloat162*)(hi + dst0);
    __nv_bfloat162* pl = (__nv_bfloat162*)(lo + dst0);
    ph[idx * 2] = a; ph[idx * 2 + 1] = b;
    pl[idx * 2] = c; pl[idx * 2 + 1] = d;
}

// ---------------- rmsnorm -> bf16 hi/lo ----------------
__global__ void __launch_bounds__(256) rmsnorm_split_kernel(const float* __restrict__ x,
                                                            const float* __restrict__ w,
                                                            __nv_bfloat16* __restrict__ yhi,
                                                            __nv_bfloat16* __restrict__ ylo) {
    int row = blockIdx.x;
    int t = threadIdx.x;
    const float4* xr = (const float4*)(x + (size_t)row * D);
    float4 xv = xr[t];
    float ss = xv.x * xv.x + xv.y * xv.y + xv.z * xv.z + xv.w * xv.w;
    #pragma unroll
    for (int o = 16; o > 0; o >>= 1) ss += __shfl_xor_sync(0xffffffffu, ss, o);
    __shared__ float red[8];
    if ((t & 31) == 0) red[t >> 5] = ss;
    __syncthreads();
    if (t < 32) {
        float v = (t < 8) ? red[t] : 0.f;
        #pragma unroll
        for (int o = 4; o > 0; o >>= 1) v += __shfl_xor_sync(0xffffffffu, v, o);
        if (t == 0) red[0] = v;
    }
    __syncthreads();
    float scale = rsqrtf(red[0] * (1.0f / (float)D) + 1e-6f);
    float4 wv = ((const float4*)w)[t];
    float o0 = xv.x * scale * wv.x, o1 = xv.y * scale * wv.y;
    float o2 = xv.z * scale * wv.z, o3 = xv.w * scale * wv.w;
    __nv_bfloat16 h0, l0, h1, l1, h2, l2, h3, l3;
    split_one(o0, h0, l0); split_one(o1, h1, l1);
    split_one(o2, h2, l2); split_one(o3, h3, l3);
    size_t base2 = (size_t)row * (D / 2) + t * 2;
    __nv_bfloat162 a; a.x = h0; a.y = h1;
    __nv_bfloat162 b; b.x = h2; b.y = h3;
    __nv_bfloat162 c; c.x = l0; c.y = l1;
    __nv_bfloat162 d; d.x = l2; d.y = l3;
    ((__nv_bfloat162*)yhi)[base2] = a; ((__nv_bfloat162*)yhi)[base2 + 1] = b;
    ((__nv_bfloat162*)ylo)[base2] = c; ((__nv_bfloat162*)ylo)[base2 + 1] = d;
}

// ---------------- scan pass 1 (fused a,s computation): per (b,chunk,d) ----------------
// reads hs, r(=sigmoid pre-gate), i; computes a,s; writes a->r, s->i in place;
// accumulates chunk aggregates Agg (prod a) and Sgg (local scan end).
__global__ void __launch_bounds__(256) scan1_fused_kernel(const float* __restrict__ hs,
                                                          float* __restrict__ r,
                                                          float* __restrict__ iv,
                                                          const float* __restrict__ alpha,
                                                          float* __restrict__ Agg,
                                                          float* __restrict__ Sgg) {
    int g = blockIdx.x * 256 + threadIdx.x;      // B*NC*D threads
    int d = g & (D - 1);
    int chunk = (g >> 10) & (NC - 1);
    int b = g >> 14;
    float coef = -8.0f * log1pf(expf(alpha[d]));
    size_t base = ((size_t)b * L + (size_t)chunk * CL) * D + d;
    float Ap = 1.f, S = 0.f;
    for (int t = 0; t < CL; t++) {
        size_t idx = base + (size_t)t * D;
        float at = expf(coef * r[idx]);
        float st = sqrtf(fmaxf(1.0f - at * at, 0.0f)) * hs[idx] * iv[idx];
        r[idx] = at;
        iv[idx] = st;
        S = fmaf(at, S, st);
        Ap *= at;
    }
    Agg[g] = Ap;
    Sgg[g] = S;
}

__global__ void __launch_bounds__(256) scan2_kernel(const float* __restrict__ Agg,
                                                    const float* __restrict__ Sgg,
                                                    float* __restrict__ Cin) {
    int g = blockIdx.x * 256 + threadIdx.x;      // B*D threads
    int d = g & (D - 1);
    int b = g >> 10;
    float carry = 0.f;
    for (int c = 0; c < NC; c++) {
        int idx = (b * NC + c) * D + d;
        Cin[idx] = carry;
        carry = fmaf(Agg[idx], carry, Sgg[idx]);
    }
}

__global__ void __launch_bounds__(256) scan3_kernel(const float* __restrict__ a,
                                                    const float* __restrict__ s,
                                                    const float* __restrict__ Cin,
                                                    const float* __restrict__ gate,
                                                    const float* __restrict__ resid,
                                                    float* __restrict__ hs2) {
    int g = blockIdx.x * 256 + threadIdx.x;
    int d = g & (D - 1);
    int chunk = (g >> 10) & (NC - 1);
    int b = g >> 14;
    size_t base = ((size_t)b * L + (size_t)chunk * CL) * D + d;
    float carry = Cin[g];
    for (int t = 0; t < CL; t++) {
        size_t idx = base + (size_t)t * D;
        carry = fmaf(a[idx], carry, s[idx]);
        hs2[idx] = fmaf(carry, gate[idx], resid[idx]);
    }
}

// ---------------- launch ----------------
extern "C" void kernel_launch(void* const* d_in, const int* in_sizes, int n_in,
                              void* d_out, int out_size) {
    const float* hidden    = (const float*)d_in[0];
    const float* alpha     = (const float*)d_in[1];
    const float* fc_w      = (const float*)d_in[2];
    const float* fc_b      = (const float*)d_in[3];
    const float* fc_r_w    = (const float*)d_in[4];
    const float* fc_r_b    = (const float*)d_in[5];
    const float* fc_i_w    = (const float*)d_in[6];
    const float* fc_i_b    = (const float*)d_in[7];
    const float* fc_gate_w = (const float*)d_in[8];
    const float* fc_gate_b = (const float*)d_in[9];
    const float* norm_w    = (const float*)d_in[10];
    const float* norm2_w   = (const float*)d_in[11];
    const float* mlp_gate_w= (const float*)d_in[12];
    const float* mlp_gate_b= (const float*)d_in[13];
    const float* mlp_fc_w  = (const float*)d_in[14];
    const float* mlp_fc_b  = (const float*)d_in[15];
    const float* out_w     = (const float*)d_in[16];
    const float* out_b     = (const float*)d_in[17];
    float* out = (float*)d_out;

    float *p_gate, *p_hs, *p_r, *p_i, *p_hs2, *p_g2, *p_Agg, *p_Sgg, *p_Cin;
    __nv_bfloat16 *p_hhi, *p_hlo, *p_f2hi, *p_f2lo, *p_whi, *p_wlo;
    cudaGetSymbolAddress((void**)&p_gate, g_gate);
    cudaGetSymbolAddress((void**)&p_hs,   g_hs);
    cudaGetSymbolAddress((void**)&p_r,    g_r);
    cudaGetSymbolAddress((void**)&p_i,    g_i);
    cudaGetSymbolAddress((void**)&p_hs2,  g_hs2);
    cudaGetSymbolAddress((void**)&p_g2,   g_g2);
    cudaGetSymbolAddress((void**)&p_Agg,  g_Agg);
    cudaGetSymbolAddress((void**)&p_Sgg,  g_Sgg);
    cudaGetSymbolAddress((void**)&p_Cin,  g_Cin);
    cudaGetSymbolAddress((void**)&p_hhi,  g_hhi);
    cudaGetSymbolAddress((void**)&p_hlo,  g_hlo);
    cudaGetSymbolAddress((void**)&p_f2hi, g_f2hi);
    cudaGetSymbolAddress((void**)&p_f2lo, g_f2lo);
    cudaGetSymbolAddress((void**)&p_whi,  g_whi);
    cudaGetSymbolAddress((void**)&p_wlo,  g_wlo);

    cudaFuncSetAttribute(gemm_mma<EPI_NONE>, cudaFuncAttributeMaxDynamicSharedMemorySize, SMEM_GEMM);
    cudaFuncSetAttribute(gemm_mma<EPI_GELU>, cudaFuncAttributeMaxDynamicSharedMemorySize, SMEM_GEMM);
    cudaFuncSetAttribute(gemm_mma<EPI_SIG >, cudaFuncAttributeMaxDynamicSharedMemorySize, SMEM_GEMM);
    cudaFuncSetAttribute(gemm_mma<EPI_MUL >, cudaFuncAttributeMaxDynamicSharedMemorySize, SMEM_GEMM);
    cudaFuncSetAttribute(gemm_mma<EPI_ADD >, cudaFuncAttributeMaxDynamicSharedMemorySize, SMEM_GEMM);

    // weight arena offsets (elems): [fc, fc_r, fc_i, fc_gate, mlp_gate(3), mlp_fc(3), out(3)]
    const size_t O_FC = 0, O_FCR = 1 * MW, O_FCI = 2 * MW, O_FCG = 3 * MW;
    const size_t O_MG = 4 * MW, O_MF = 7 * MW, O_OW = 10 * MW;

    // Launch order chosen so ncu (-s 5 -c 1) profiles launch #6 = first-layer SIG GEMM.
    // (1) split 4 small weights
    split_small4<<<dim3(MW / 1024, 4), 256>>>(fc_w, fc_r_w, fc_i_w, fc_gate_w, p_whi, p_wlo);
    // (2) split 3 big weights
    split_big3<<<dim3(3 * MW / 1024, 3), 256>>>(mlp_gate_w, mlp_fc_w, out_w, p_whi, p_wlo);
    // (3) rmsnorm1 -> h hi/lo
    rmsnorm_split_kernel<<<N, 256>>>(hidden, norm_w, p_hhi, p_hlo);

    // (4-7) first-layer GEMMs (O = D)
    dim3 g1(D / BN, N / BM);                 // (4, 256)
    gemm_mma<EPI_GELU><<<g1, 256, SMEM_GEMM>>>(p_hhi, p_hlo, p_whi + O_FCG, p_wlo + O_FCG, fc_gate_b, nullptr, p_gate, nullptr, nullptr, D);
    gemm_mma<EPI_NONE><<<g1, 256, SMEM_GEMM>>>(p_hhi, p_hlo, p_whi + O_FC,  p_wlo + O_FC,  fc_b,      nullptr, p_hs,   nullptr, nullptr, D);
    gemm_mma<EPI_SIG ><<<g1, 256, SMEM_GEMM>>>(p_hhi, p_hlo, p_whi + O_FCR, p_wlo + O_FCR, fc_r_b,    nullptr, p_r,    nullptr, nullptr, D);
    gemm_mma<EPI_SIG ><<<g1, 256, SMEM_GEMM>>>(p_hhi, p_hlo, p_whi + O_FCI, p_wlo + O_FCI, fc_i_b,    nullptr, p_i,    nullptr, nullptr, D);

    // (8-10) fused a,s + chunked linear recurrence + fused gate/residual
    scan1_fused_kernel<<<(B * NC * D) / 256, 256>>>(p_hs, p_r, p_i, alpha, p_Agg, p_Sgg);
    scan2_kernel<<<(B * D) / 256, 256>>>(p_Agg, p_Sgg, p_Cin);
    scan3_kernel<<<(B * NC * D) / 256, 256>>>(p_r, p_i, p_Cin, p_gate, hidden, p_hs2);

    // (11) rmsnorm2 -> h hi/lo (reuse buffers)
    rmsnorm_split_kernel<<<N, 256>>>(p_hs2, norm2_w, p_hhi, p_hlo);

    // (12-13) MLP GEMMs (O = 3D)
    dim3 g2(3 * D / BN, N / BM);             // (12, 256)
    gemm_mma<EPI_GELU><<<g2, 256, SMEM_GEMM>>>(p_hhi, p_hlo, p_whi + O_MG, p_wlo + O_MG, mlp_gate_b, nullptr, p_g2, nullptr, nullptr, D);
    gemm_mma<EPI_MUL ><<<g2, 256, SMEM_GEMM>>>(p_hhi, p_hlo, p_whi + O_MF, p_wlo + O_MF, mlp_fc_b,   p_g2,    nullptr, p_f2hi, p_f2lo, D);

    // (14) output projection + residual (K = 3D)
    gemm_mma<EPI_ADD><<<g1, 256, SMEM_GEMM>>>(p_f2hi, p_f2lo, p_whi + O_OW, p_wlo + O_OW, out_b, p_hs2, out, nullptr, nullptr, 3 * D);
}